// round 15
// baseline (speedup 1.0000x reference)
#include <cuda_runtime.h>
#include <cuda_fp16.h>
#include <math.h>
#include <stdint.h>

// Problem constants
#define BATCH   8
#define DIM     1024
#define HW      1024
#define NROW    8192
#define NCODE   8192
#define ZQ_ELEMS (BATCH*DIM*HW)
#define OFF_LOSS  ZQ_ELEMS
#define OFF_PERP  (ZQ_ELEMS + 1)
#define OFF_IDX   (ZQ_ELEMS + 2)

#define ESCALE 512.0f
#define MARGIN 1e-3f
#define NTILES 64
#define KSLOT  8
#define WCAND  256

// ---------------- device scratch ---------------------------------------------
__device__ float   g_zflat[(size_t)NROW * DIM];
__device__ __half  g_zh[(size_t)NROW * DIM];
__device__ __half  g_eh[(size_t)NCODE * DIM];
__device__ float   g_partS[(size_t)NROW * 32];
__device__ float   g_S[NROW];
__device__ float   g_T[NCODE];
__device__ float   g_tmin[(size_t)NROW * NTILES];
__device__ int     g_tcnt[(size_t)NROW * NTILES];
__device__ unsigned long long g_tcand[(size_t)NROW * NTILES * KSLOT];
__device__ int     g_idx[NROW];
__device__ int     g_hist[NCODE];
__device__ double  g_loss;
__device__ int     g_rowdone[NROW / 128];
__device__ int     g_gdone;

// ---------------- PTX helpers -------------------------------------------------
__device__ __forceinline__ uint32_t smem_u32(const void* p) {
    uint32_t a;
    asm("{ .reg .u64 t; cvta.to.shared.u64 t, %1; cvt.u32.u64 %0, t; }" : "=r"(a) : "l"(p));
    return a;
}
__device__ __forceinline__ void cp_async16(uint32_t saddr, const void* gptr) {
    asm volatile("cp.async.cg.shared.global [%0], [%1], 16;" :: "r"(saddr), "l"(gptr));
}
__device__ __forceinline__ void cp_commit() { asm volatile("cp.async.commit_group;" ::: "memory"); }
__device__ __forceinline__ void cp_wait0()  { asm volatile("cp.async.wait_group 0;" ::: "memory"); }

__device__ __forceinline__ void ldsm_x4(uint32_t* r, uint32_t addr) {
    asm volatile("ldmatrix.sync.aligned.m8n8.x4.shared.b16 {%0,%1,%2,%3}, [%4];"
                 : "=r"(r[0]), "=r"(r[1]), "=r"(r[2]), "=r"(r[3]) : "r"(addr));
}
__device__ __forceinline__ void mma16816(float* d, const uint32_t* a, uint32_t b0, uint32_t b1) {
    asm volatile("mma.sync.aligned.m16n8k16.row.col.f32.f16.f16.f32 "
                 "{%0,%1,%2,%3}, {%4,%5,%6,%7}, {%8,%9}, {%0,%1,%2,%3};"
                 : "+f"(d[0]), "+f"(d[1]), "+f"(d[2]), "+f"(d[3])
                 : "r"(a[0]), "r"(a[1]), "r"(a[2]), "r"(a[3]), "r"(b0), "r"(b1));
}
__device__ __forceinline__ unsigned long long packvc(float v, int code) {
    return ((unsigned long long)__float_as_uint(v) << 32) | (unsigned)code;
}
__device__ __forceinline__ float unpackv(unsigned long long p) {
    return __uint_as_float((unsigned)(p >> 32));
}

// ---------------- kernel 1: transpose z -> zflat (fp32+fp16) + partial S -----
__global__ void vq_transpose_kernel(const float* __restrict__ z) {
    __shared__ float tile[32][33];
    int b = blockIdx.z;
    int hw0 = blockIdx.x * 32;
    int c0  = blockIdx.y * 32;
    const float* src = z + ((size_t)b << 20);
    float* dst = g_zflat + ((size_t)b << 20);
    __half* dsth = g_zh + ((size_t)b << 20);
    #pragma unroll
    for (int r = threadIdx.y; r < 32; r += 8)
        tile[r][threadIdx.x] = src[(size_t)(c0 + r) * HW + hw0 + threadIdx.x];
    __syncthreads();
    #pragma unroll
    for (int r = threadIdx.y; r < 32; r += 8) {
        float v = tile[threadIdx.x][r];
        size_t o = (size_t)(hw0 + r) * DIM + c0 + threadIdx.x;
        dst[o]  = v;
        dsth[o] = __float2half_rn(v);
        float sq = v * v;
        #pragma unroll
        for (int s = 16; s; s >>= 1) sq += __shfl_down_sync(0xffffffffu, sq, s);
        if (threadIdx.x == 0)
            g_partS[(((size_t)(b << 10) | (hw0 + r)) << 5) | blockIdx.y] = sq;
    }
}

// ---------------- kernel 2: S combine; emb norms + fp16 convert; zero state --
__global__ void vq_rowsum_kernel(const float* __restrict__ emb) {
    int gt   = blockIdx.x * blockDim.x + threadIdx.x;
    if (gt < NROW / 128) g_rowdone[gt] = 0;
    if (gt == NROW / 128) g_gdone = 0;
    int gw   = gt >> 5;
    int lane = threadIdx.x & 31;
    if (gw >= NROW + NCODE) return;
    if (gw < NROW) {
        float s = g_partS[((size_t)gw << 5) | lane];
        #pragma unroll
        for (int o = 16; o; o >>= 1) s += __shfl_down_sync(0xffffffffu, s, o);
        if (lane == 0) {
            g_S[gw] = s;
            if (gw == 0) g_loss = 0.0;
        }
        return;
    }
    int row = gw - NROW;
    const float4* s4 = (const float4*)(emb + (size_t)row * DIM);
    __half2* eh2 = (__half2*)(g_eh + (size_t)row * DIM);
    float acc = 0.f;
    #pragma unroll 4
    for (int i = lane; i < DIM / 4; i += 32) {
        float4 v = s4[i];
        eh2[i * 2]     = __floats2half2_rn(v.x * ESCALE, v.y * ESCALE);
        eh2[i * 2 + 1] = __floats2half2_rn(v.z * ESCALE, v.w * ESCALE);
        acc += v.x * v.x + v.y * v.y + v.z * v.z + v.w * v.w;
    }
    #pragma unroll
    for (int o = 16; o; o >>= 1) acc += __shfl_down_sync(0xffffffffu, acc, o);
    if (lane == 0) { g_T[row] = acc; g_hist[row] = 0; }
}

// ---------------- kernel 3: fp16 HMMA GEMM + fused epilogue + inline scan ----
#define AS_OFF(s) ((s) * 10240u)
#define BS_OFF(s) (20480u + (s) * 10240u)

__global__ __launch_bounds__(256, 2)
void vq_mm_kernel(const float* __restrict__ emb, float* __restrict__ out) {
    __shared__ __align__(128) uint8_t smem[40960];
    __shared__ int s_flag;
    const uint32_t sb = smem_u32(smem);
    const int tid = threadIdx.x;
    const int lane = tid & 31, wid = tid >> 5;
    const int warpM = wid >> 2, warpN = wid & 3;
    const int rowBase  = blockIdx.y * 128;
    const int codeBase = blockIdx.x * 128;
    const int tileN = blockIdx.x;

    const int ldrow = tid >> 1;
    const int ldc0  = (tid & 1) * 2;
    const __half* gA = g_zh + (size_t)(rowBase + ldrow) * DIM + ldc0 * 8;
    const __half* gB = g_eh + (size_t)(codeBase + ldrow) * DIM + ldc0 * 8;
    const uint32_t stA = (uint32_t)ldrow * 80u + (uint32_t)ldc0 * 16u;

    const uint32_t a_base = (uint32_t)((warpM * 64 + (lane & 15)) * 80 + ((lane >> 4) * 8) * 2);
    const int grp = lane >> 3;
    const uint32_t b_base = (uint32_t)((warpN * 32 + ((grp >> 1) * 8) + (lane & 7)) * 80
                                       + ((grp & 1) * 8) * 2);

    float acc[4][4][4];
    #pragma unroll
    for (int i = 0; i < 4; i++)
        #pragma unroll
        for (int j = 0; j < 4; j++)
            #pragma unroll
            for (int k = 0; k < 4; k++) acc[i][j][k] = 0.f;

    {
        uint32_t a0 = sb + AS_OFF(0) + stA;
        cp_async16(a0,      gA);
        cp_async16(a0 + 16, gA + 8);
        uint32_t b0 = sb + BS_OFF(0) + stA;
        cp_async16(b0,      gB);
        cp_async16(b0 + 16, gB + 8);
        cp_commit();
    }

    #pragma unroll 1
    for (int kt = 0; kt < 32; kt++) {
        cp_wait0();
        __syncthreads();
        if (kt < 31) {
            int k0 = (kt + 1) * 32;
            int s  = (kt + 1) & 1;
            uint32_t a0 = sb + AS_OFF(s) + stA;
            cp_async16(a0,      gA + k0);
            cp_async16(a0 + 16, gA + k0 + 8);
            uint32_t b0 = sb + BS_OFF(s) + stA;
            cp_async16(b0,      gB + k0);
            cp_async16(b0 + 16, gB + k0 + 8);
            cp_commit();
        }
        const int s = kt & 1;
        const uint32_t As0 = sb + AS_OFF(s) + a_base;
        const uint32_t Bs0 = sb + BS_OFF(s) + b_base;
        #pragma unroll
        for (int ks = 0; ks < 2; ks++) {
            uint32_t a[4][4], b[2][4];
            #pragma unroll
            for (int mt = 0; mt < 4; mt++) ldsm_x4(a[mt], As0 + mt * 16 * 80 + ks * 32);
            #pragma unroll
            for (int pr = 0; pr < 2; pr++)  ldsm_x4(b[pr], Bs0 + pr * 16 * 80 + ks * 32);
            #pragma unroll
            for (int mt = 0; mt < 4; mt++)
                #pragma unroll
                for (int nt = 0; nt < 4; nt++)
                    mma16816(acc[mt][nt], a[mt], b[nt >> 1][(nt & 1) * 2], b[nt >> 1][(nt & 1) * 2 + 1]);
        }
    }
    __syncthreads();

    // ---- fused epilogue: per-row tile min + margin candidates ----
    float* sWmin = (float*)smem;
    float* sMin  = (float*)(smem + 2048);
    int*   sCnt  = (int*)(smem + 2560);
    unsigned long long* sCand = (unsigned long long*)(smem + 3072);

    const float inv2 = 2.0f / ESCALE;
    float Sv[4][2], Tv[4][2];
    #pragma unroll
    for (int mt = 0; mt < 4; mt++) {
        int r0 = rowBase + warpM * 64 + mt * 16 + (lane >> 2);
        Sv[mt][0] = g_S[r0]; Sv[mt][1] = g_S[r0 + 8];
    }
    #pragma unroll
    for (int nt = 0; nt < 4; nt++) {
        int c0 = codeBase + warpN * 32 + nt * 8 + (lane & 3) * 2;
        Tv[nt][0] = g_T[c0]; Tv[nt][1] = g_T[c0 + 1];
    }

    #pragma unroll
    for (int mt = 0; mt < 4; mt++)
        #pragma unroll
        for (int nt = 0; nt < 4; nt++)
            #pragma unroll
            for (int half = 0; half < 2; half++)
                #pragma unroll
                for (int j = 0; j < 2; j++)
                    acc[mt][nt][half * 2 + j] =
                        __fsub_rn(__fadd_rn(Sv[mt][half], Tv[nt][j]),
                                  inv2 * acc[mt][nt][half * 2 + j]);

    #pragma unroll
    for (int mt = 0; mt < 4; mt++) {
        #pragma unroll
        for (int half = 0; half < 2; half++) {
            float mn = acc[mt][0][half * 2];
            #pragma unroll
            for (int nt = 0; nt < 4; nt++)
                #pragma unroll
                for (int j = 0; j < 2; j++)
                    mn = fminf(mn, acc[mt][nt][half * 2 + j]);
            mn = fminf(mn, __shfl_xor_sync(0xffffffffu, mn, 1));
            mn = fminf(mn, __shfl_xor_sync(0xffffffffu, mn, 2));
            if ((lane & 3) == 0) {
                int rl = warpM * 64 + mt * 16 + (lane >> 2) + half * 8;
                sWmin[(rl << 2) | warpN] = mn;
            }
        }
    }
    __syncthreads();
    if (tid < 128) {
        float m = fminf(fminf(sWmin[tid * 4], sWmin[tid * 4 + 1]),
                        fminf(sWmin[tid * 4 + 2], sWmin[tid * 4 + 3]));
        sMin[tid] = m;
        sCnt[tid] = 0;
    }
    __syncthreads();

    #pragma unroll
    for (int mt = 0; mt < 4; mt++) {
        #pragma unroll
        for (int half = 0; half < 2; half++) {
            int rl = warpM * 64 + mt * 16 + (lane >> 2) + half * 8;
            float thr = sMin[rl] + MARGIN;
            #pragma unroll
            for (int nt = 0; nt < 4; nt++) {
                int c0 = warpN * 32 + nt * 8 + (lane & 3) * 2;
                #pragma unroll
                for (int j = 0; j < 2; j++) {
                    float v = acc[mt][nt][half * 2 + j];
                    if (v <= thr) {
                        int p = atomicAdd(&sCnt[rl], 1);
                        if (p < KSLOT) sCand[rl * KSLOT + p] = packvc(v, codeBase + c0 + j);
                    }
                }
            }
        }
    }
    __syncthreads();

    // write out used slots only
    if (tid < 128) {
        int cnt = sCnt[tid];
        size_t o = (size_t)(rowBase + tid) * NTILES + tileN;
        g_tmin[o] = sMin[tid];
        g_tcnt[o] = cnt;
        int c = cnt < KSLOT ? cnt : KSLOT;
        size_t co = o * KSLOT;
        for (int j = 0; j < c; j++) g_tcand[co + j] = sCand[tid * KSLOT + j];
    }
    __threadfence();
    __syncthreads();

    // ---- completion counter: last CTA for this row-block runs the scan ----
    if (tid == 0)
        s_flag = (atomicAdd(&g_rowdone[blockIdx.y], 1) == NTILES - 1) ? 1 : 0;
    __syncthreads();
    if (!s_flag) return;
    __threadfence();

    // ---- inline scan: warp-per-row, 16 rows per warp ----
    int*   qCand = (int*)smem;                       // 8 * 256 ints = 8 KB
    float* qTval = (float*)(smem + 8192);            // 8 KB
    int*   qCnt  = (int*)(smem + 16384);             // 8 ints
    int*   qOvf  = (int*)(smem + 16416);             // 8 ints
    const int w = wid;

    for (int it = 0; it < 16; it++) {
        const int n = rowBase + w + it * 8;
        if (lane == 0) { qCnt[w] = 0; qOvf[w] = 0; }
        __syncwarp();

        const float* tmrow = g_tmin + (size_t)n * NTILES;
        float m0 = tmrow[lane], m1 = tmrow[lane + 32];
        float mn = fminf(m0, m1);
        #pragma unroll
        for (int o = 16; o; o >>= 1) mn = fminf(mn, __shfl_xor_sync(0xffffffffu, mn, o));
        const float thr = mn + MARGIN;

        #pragma unroll
        for (int tt = 0; tt < 2; tt++) {
            int t = lane + tt * 32;
            float tm = tt ? m1 : m0;
            if (tm <= thr) {
                int cnt = g_tcnt[(size_t)n * NTILES + t];
                if (cnt <= KSLOT) {
                    size_t base = ((size_t)n * NTILES + t) * KSLOT;
                    for (int c = 0; c < cnt; c++) {
                        unsigned long long cd = g_tcand[base + c];
                        if (unpackv(cd) <= thr) {
                            int p = atomicAdd(&qCnt[w], 1);
                            if (p < WCAND) {
                                int code = (int)(cd & 0xffffffffu);
                                qCand[w * WCAND + p] = code;
                                qTval[w * WCAND + p] = g_T[code];
                            } else qOvf[w] = 1;
                        }
                    }
                } else {
                    for (int j = 0; j < 128; j++) {
                        int p = atomicAdd(&qCnt[w], 1);
                        if (p < WCAND) {
                            int code = t * 128 + j;
                            qCand[w * WCAND + p] = code;
                            qTval[w * WCAND + p] = g_T[code];
                        } else qOvf[w] = 1;
                    }
                }
            }
        }
        __syncwarp();

        const bool full = qOvf[w] != 0;
        const int total = full ? NCODE : min(qCnt[w], WCAND);

        if (!full && total == 1) {
            if (lane == 0) {
                int bk = qCand[w * WCAND];
                g_idx[n] = bk;
                out[OFF_IDX + n] = (float)bk;
                atomicAdd(&g_hist[bk], 1);
            }
            continue;
        }

        const float4* zr = (const float4*)(g_zflat + (size_t)n * DIM);
        float4 zv[8];
        #pragma unroll
        for (int j = 0; j < 8; j++) zv[j] = zr[lane + 32 * j];
        const float S = g_S[n];

        float bd = __int_as_float(0x7f800000);
        int   bk = 0x7fffffff;

        for (int c = 0; c < total; c++) {
            int k = full ? c : qCand[w * WCAND + c];
            const float4* er = (const float4*)(emb + (size_t)k * DIM);
            float p = 0.f;
            #pragma unroll
            for (int j = 0; j < 8; j++) {
                float4 e = er[lane + 32 * j];
                p = fmaf(zv[j].x, e.x, p);
                p = fmaf(zv[j].y, e.y, p);
                p = fmaf(zv[j].z, e.z, p);
                p = fmaf(zv[j].w, e.w, p);
            }
            #pragma unroll
            for (int o = 16; o; o >>= 1) p += __shfl_down_sync(0xffffffffu, p, o);
            if (lane == 0) {
                float T = full ? g_T[k] : qTval[w * WCAND + c];
                float d = __fsub_rn(__fadd_rn(S, T), 2.0f * p);
                if (d < bd || (d == bd && k < bk)) { bd = d; bk = k; }
            }
        }
        if (lane == 0) {
            g_idx[n] = bk;
            out[OFF_IDX + n] = (float)bk;
            atomicAdd(&g_hist[bk], 1);
        }
    }
}

// ---------------- kernel 5: gather + STE + loss + fused finalize -------------
__global__ void vq_gather_kernel(const float* __restrict__ z,
                                 const float* __restrict__ emb,
                                 float* __restrict__ out) {
    __shared__ float warpsum[8];
    __shared__ int s_last;
    int t4 = blockIdx.x * blockDim.x + threadIdx.x;
    int base = t4 * 4;
    int hw0 = base & 1023;
    int c   = (base >> 10) & 1023;
    int b   = base >> 20;

    float4 zv = *(const float4*)(z + base);
    float4 ov;
    float sq = 0.f;
    {
        int code = g_idx[(b << 10) | hw0];
        float diff = __fsub_rn(emb[(size_t)code * DIM + c], zv.x);
        ov.x = __fadd_rn(zv.x, diff); sq = fmaf(diff, diff, sq);
    }
    {
        int code = g_idx[(b << 10) | (hw0 + 1)];
        float diff = __fsub_rn(emb[(size_t)code * DIM + c], zv.y);
        ov.y = __fadd_rn(zv.y, diff); sq = fmaf(diff, diff, sq);
    }
    {
        int code = g_idx[(b << 10) | (hw0 + 2)];
        float diff = __fsub_rn(emb[(size_t)code * DIM + c], zv.z);
        ov.z = __fadd_rn(zv.z, diff); sq = fmaf(diff, diff, sq);
    }
    {
        int code = g_idx[(b << 10) | (hw0 + 3)];
        float diff = __fsub_rn(emb[(size_t)code * DIM + c], zv.w);
        ov.w = __fadd_rn(zv.w, diff); sq = fmaf(diff, diff, sq);
    }
    *(float4*)(out + base) = ov;

    #pragma unroll
    for (int o = 16; o; o >>= 1) sq += __shfl_down_sync(0xffffffffu, sq, o);
    int lane = threadIdx.x & 31, wid = threadIdx.x >> 5;
    if (lane == 0) warpsum[wid] = sq;
    if (threadIdx.x == 0) s_last = 0;
    __syncthreads();
    if (wid == 0) {
        float v = (lane < 8) ? warpsum[lane] : 0.f;
        #pragma unroll
        for (int o = 4; o; o >>= 1) v += __shfl_down_sync(0xffffffffu, v, o);
        if (lane == 0) {
            atomicAdd(&g_loss, (double)v);
            __threadfence();
            if (atomicAdd(&g_gdone, 1) == (int)gridDim.x - 1) s_last = 1;
        }
    }
    __syncthreads();
    if (!s_last) return;
    __threadfence();

    // ---- fused finalize (runs in the last gather block) ----
    float s = 0.f;
    for (int k = threadIdx.x; k < NCODE; k += 256) {
        float cc = (float)g_hist[k];
        float p = cc * (1.0f / (float)NROW);
        s += p * logf(p + 1e-10f);
    }
    #pragma unroll
    for (int o = 16; o; o >>= 1) s += __shfl_down_sync(0xffffffffu, s, o);
    if (lane == 0) warpsum[wid] = s;
    __syncthreads();
    if (wid == 0) {
        float v = (lane < 8) ? warpsum[lane] : 0.f;
        #pragma unroll
        for (int o = 4; o; o >>= 1) v += __shfl_down_sync(0xffffffffu, v, o);
        if (lane == 0) {
            out[OFF_PERP] = expf(-v);
            double m = g_loss / (double)ZQ_ELEMS;
            float mf = (float)m;
            out[OFF_LOSS] = __fadd_rn(mf, 0.25f * mf);
        }
    }
}

// ---------------- launch ------------------------------------------------------
extern "C" void kernel_launch(void* const* d_in, const int* in_sizes, int n_in,
                              void* d_out, int out_size) {
    const float* z   = (const float*)d_in[0];
    const float* emb = (const float*)d_in[1];
    float* out = (float*)d_out;
    (void)in_sizes; (void)n_in; (void)out_size;

    dim3 tb(32, 8);
    dim3 tg(32, 32, BATCH);
    vq_transpose_kernel<<<tg, tb>>>(z);

    vq_rowsum_kernel<<<(NROW + NCODE) * 32 / 256, 256>>>(emb);

    dim3 mg(NCODE / 128, NROW / 128);
    vq_mm_kernel<<<mg, 256>>>(emb, out);

    vq_gather_kernel<<<ZQ_ELEMS / 4 / 256, 256>>>(z, emb, out);
}

// round 16
// speedup vs baseline: 1.1302x; 1.1302x over previous
#include <cuda_runtime.h>
#include <cuda_fp16.h>
#include <math.h>
#include <stdint.h>

// Problem constants
#define BATCH   8
#define DIM     1024
#define HW      1024
#define NROW    8192
#define NCODE   8192
#define ZQ_ELEMS (BATCH*DIM*HW)
#define OFF_LOSS  ZQ_ELEMS
#define OFF_PERP  (ZQ_ELEMS + 1)
#define OFF_IDX   (ZQ_ELEMS + 2)

#define ESCALE 512.0f
#define MARGIN 1e-3f
#define NTILES 64
#define KSLOT  8
#define WCAND  256

// ---------------- device scratch ---------------------------------------------
__device__ float   g_zflat[(size_t)NROW * DIM];
__device__ __half  g_zh[(size_t)NROW * DIM];
__device__ __half  g_eh[(size_t)NCODE * DIM];
__device__ float   g_partS[(size_t)NROW * 32];
__device__ float   g_S[NROW];
__device__ float   g_T[NCODE];
__device__ float   g_tmin[(size_t)NROW * NTILES];
__device__ int     g_tcnt[(size_t)NROW * NTILES];
__device__ unsigned long long g_tcand[(size_t)NROW * NTILES * KSLOT];
__device__ int     g_idx[NROW];
__device__ int     g_hist[NCODE];
__device__ double  g_loss;

// ---------------- PTX helpers -------------------------------------------------
__device__ __forceinline__ uint32_t smem_u32(const void* p) {
    uint32_t a;
    asm("{ .reg .u64 t; cvta.to.shared.u64 t, %1; cvt.u32.u64 %0, t; }" : "=r"(a) : "l"(p));
    return a;
}
__device__ __forceinline__ void cp_async16(uint32_t saddr, const void* gptr) {
    asm volatile("cp.async.cg.shared.global [%0], [%1], 16;" :: "r"(saddr), "l"(gptr));
}
__device__ __forceinline__ void cp_commit() { asm volatile("cp.async.commit_group;" ::: "memory"); }
__device__ __forceinline__ void cp_wait0()  { asm volatile("cp.async.wait_group 0;" ::: "memory"); }

__device__ __forceinline__ void ldsm_x4(uint32_t* r, uint32_t addr) {
    asm volatile("ldmatrix.sync.aligned.m8n8.x4.shared.b16 {%0,%1,%2,%3}, [%4];"
                 : "=r"(r[0]), "=r"(r[1]), "=r"(r[2]), "=r"(r[3]) : "r"(addr));
}
__device__ __forceinline__ void mma16816(float* d, const uint32_t* a, uint32_t b0, uint32_t b1) {
    asm volatile("mma.sync.aligned.m16n8k16.row.col.f32.f16.f16.f32 "
                 "{%0,%1,%2,%3}, {%4,%5,%6,%7}, {%8,%9}, {%0,%1,%2,%3};"
                 : "+f"(d[0]), "+f"(d[1]), "+f"(d[2]), "+f"(d[3])
                 : "r"(a[0]), "r"(a[1]), "r"(a[2]), "r"(a[3]), "r"(b0), "r"(b1));
}
__device__ __forceinline__ unsigned long long packvc(float v, int code) {
    return ((unsigned long long)__float_as_uint(v) << 32) | (unsigned)code;
}
__device__ __forceinline__ float unpackv(unsigned long long p) {
    return __uint_as_float((unsigned)(p >> 32));
}

// ---------------- kernel 1: transpose z -> zflat (fp32+fp16) + partial S -----
__global__ void vq_transpose_kernel(const float* __restrict__ z) {
    __shared__ float tile[32][33];
    int b = blockIdx.z;
    int hw0 = blockIdx.x * 32;
    int c0  = blockIdx.y * 32;
    const float* src = z + ((size_t)b << 20);
    float* dst = g_zflat + ((size_t)b << 20);
    __half* dsth = g_zh + ((size_t)b << 20);
    #pragma unroll
    for (int r = threadIdx.y; r < 32; r += 8)
        tile[r][threadIdx.x] = src[(size_t)(c0 + r) * HW + hw0 + threadIdx.x];
    __syncthreads();
    #pragma unroll
    for (int r = threadIdx.y; r < 32; r += 8) {
        float v = tile[threadIdx.x][r];
        size_t o = (size_t)(hw0 + r) * DIM + c0 + threadIdx.x;
        dst[o]  = v;
        dsth[o] = __float2half_rn(v);
        float sq = v * v;
        #pragma unroll
        for (int s = 16; s; s >>= 1) sq += __shfl_down_sync(0xffffffffu, sq, s);
        if (threadIdx.x == 0)
            g_partS[(((size_t)(b << 10) | (hw0 + r)) << 5) | blockIdx.y] = sq;
    }
}

// ---------------- kernel 2: S combine; emb norms + fp16 convert; zero hist ---
__global__ void vq_rowsum_kernel(const float* __restrict__ emb) {
    int gw   = (blockIdx.x * blockDim.x + threadIdx.x) >> 5;
    int lane = threadIdx.x & 31;
    if (gw >= NROW + NCODE) return;
    if (gw < NROW) {
        float s = g_partS[((size_t)gw << 5) | lane];
        #pragma unroll
        for (int o = 16; o; o >>= 1) s += __shfl_down_sync(0xffffffffu, s, o);
        if (lane == 0) {
            g_S[gw] = s;
            if (gw == 0) g_loss = 0.0;
        }
        return;
    }
    int row = gw - NROW;
    const float4* s4 = (const float4*)(emb + (size_t)row * DIM);
    __half2* eh2 = (__half2*)(g_eh + (size_t)row * DIM);
    float acc = 0.f;
    #pragma unroll 4
    for (int i = lane; i < DIM / 4; i += 32) {
        float4 v = s4[i];
        eh2[i * 2]     = __floats2half2_rn(v.x * ESCALE, v.y * ESCALE);
        eh2[i * 2 + 1] = __floats2half2_rn(v.z * ESCALE, v.w * ESCALE);
        acc += v.x * v.x + v.y * v.y + v.z * v.z + v.w * v.w;
    }
    #pragma unroll
    for (int o = 16; o; o >>= 1) acc += __shfl_down_sync(0xffffffffu, acc, o);
    if (lane == 0) { g_T[row] = acc; g_hist[row] = 0; }
}

// ---------------- kernel 3: fp16 HMMA GEMM (R10 verbatim - FROZEN mainloop) --
#define AS_OFF(s) ((s) * 10240u)
#define BS_OFF(s) (20480u + (s) * 10240u)

__global__ __launch_bounds__(256, 2)
void vq_mm_kernel() {
    __shared__ __align__(128) uint8_t smem[40960];
    const uint32_t sb = smem_u32(smem);
    const int tid = threadIdx.x;
    const int lane = tid & 31, wid = tid >> 5;
    const int warpM = wid >> 2, warpN = wid & 3;
    const int rowBase  = blockIdx.y * 128;
    const int codeBase = blockIdx.x * 128;
    const int tileN = blockIdx.x;

    const int ldrow = tid >> 1;
    const int ldc0  = (tid & 1) * 2;
    const __half* gA = g_zh + (size_t)(rowBase + ldrow) * DIM + ldc0 * 8;
    const __half* gB = g_eh + (size_t)(codeBase + ldrow) * DIM + ldc0 * 8;
    const uint32_t stA = (uint32_t)ldrow * 80u + (uint32_t)ldc0 * 16u;

    const uint32_t a_base = (uint32_t)((warpM * 64 + (lane & 15)) * 80 + ((lane >> 4) * 8) * 2);
    const int grp = lane >> 3;
    const uint32_t b_base = (uint32_t)((warpN * 32 + ((grp >> 1) * 8) + (lane & 7)) * 80
                                       + ((grp & 1) * 8) * 2);

    float acc[4][4][4];
    #pragma unroll
    for (int i = 0; i < 4; i++)
        #pragma unroll
        for (int j = 0; j < 4; j++)
            #pragma unroll
            for (int k = 0; k < 4; k++) acc[i][j][k] = 0.f;

    {
        uint32_t a0 = sb + AS_OFF(0) + stA;
        cp_async16(a0,      gA);
        cp_async16(a0 + 16, gA + 8);
        uint32_t b0 = sb + BS_OFF(0) + stA;
        cp_async16(b0,      gB);
        cp_async16(b0 + 16, gB + 8);
        cp_commit();
    }

    #pragma unroll 1
    for (int kt = 0; kt < 32; kt++) {
        cp_wait0();
        __syncthreads();
        if (kt < 31) {
            int k0 = (kt + 1) * 32;
            int s  = (kt + 1) & 1;
            uint32_t a0 = sb + AS_OFF(s) + stA;
            cp_async16(a0,      gA + k0);
            cp_async16(a0 + 16, gA + k0 + 8);
            uint32_t b0 = sb + BS_OFF(s) + stA;
            cp_async16(b0,      gB + k0);
            cp_async16(b0 + 16, gB + k0 + 8);
            cp_commit();
        }
        const int s = kt & 1;
        const uint32_t As0 = sb + AS_OFF(s) + a_base;
        const uint32_t Bs0 = sb + BS_OFF(s) + b_base;
        #pragma unroll
        for (int ks = 0; ks < 2; ks++) {
            uint32_t a[4][4], b[2][4];
            #pragma unroll
            for (int mt = 0; mt < 4; mt++) ldsm_x4(a[mt], As0 + mt * 16 * 80 + ks * 32);
            #pragma unroll
            for (int pr = 0; pr < 2; pr++)  ldsm_x4(b[pr], Bs0 + pr * 16 * 80 + ks * 32);
            #pragma unroll
            for (int mt = 0; mt < 4; mt++)
                #pragma unroll
                for (int nt = 0; nt < 4; nt++)
                    mma16816(acc[mt][nt], a[mt], b[nt >> 1][(nt & 1) * 2], b[nt >> 1][(nt & 1) * 2 + 1]);
        }
    }
    __syncthreads();

    // ---- lean fused epilogue: per-row tile min + margin candidates ----
    float* sWmin = (float*)smem;
    float* sMin  = (float*)(smem + 2048);
    int*   sCnt  = (int*)(smem + 2560);
    unsigned long long* sCand = (unsigned long long*)(smem + 3072);

    const float inv2 = 2.0f / ESCALE;
    float Sv[4][2], Tv[4][2];
    #pragma unroll
    for (int mt = 0; mt < 4; mt++) {
        int r0 = rowBase + warpM * 64 + mt * 16 + (lane >> 2);
        Sv[mt][0] = g_S[r0]; Sv[mt][1] = g_S[r0 + 8];
    }
    #pragma unroll
    for (int nt = 0; nt < 4; nt++) {
        int c0 = codeBase + warpN * 32 + nt * 8 + (lane & 3) * 2;
        Tv[nt][0] = g_T[c0]; Tv[nt][1] = g_T[c0 + 1];
    }

    #pragma unroll
    for (int mt = 0; mt < 4; mt++)
        #pragma unroll
        for (int nt = 0; nt < 4; nt++)
            #pragma unroll
            for (int half = 0; half < 2; half++)
                #pragma unroll
                for (int j = 0; j < 2; j++)
                    acc[mt][nt][half * 2 + j] =
                        __fsub_rn(__fadd_rn(Sv[mt][half], Tv[nt][j]),
                                  inv2 * acc[mt][nt][half * 2 + j]);

    #pragma unroll
    for (int mt = 0; mt < 4; mt++) {
        #pragma unroll
        for (int half = 0; half < 2; half++) {
            float mn = acc[mt][0][half * 2];
            #pragma unroll
            for (int nt = 0; nt < 4; nt++)
                #pragma unroll
                for (int j = 0; j < 2; j++)
                    mn = fminf(mn, acc[mt][nt][half * 2 + j]);
            mn = fminf(mn, __shfl_xor_sync(0xffffffffu, mn, 1));
            mn = fminf(mn, __shfl_xor_sync(0xffffffffu, mn, 2));
            if ((lane & 3) == 0) {
                int rl = warpM * 64 + mt * 16 + (lane >> 2) + half * 8;
                sWmin[(rl << 2) | warpN] = mn;
            }
        }
    }
    __syncthreads();
    if (tid < 128) {
        float m = fminf(fminf(sWmin[tid * 4], sWmin[tid * 4 + 1]),
                        fminf(sWmin[tid * 4 + 2], sWmin[tid * 4 + 3]));
        sMin[tid] = m;
        sCnt[tid] = 0;
    }
    __syncthreads();

    #pragma unroll
    for (int mt = 0; mt < 4; mt++) {
        #pragma unroll
        for (int half = 0; half < 2; half++) {
            int rl = warpM * 64 + mt * 16 + (lane >> 2) + half * 8;
            float thr = sMin[rl] + MARGIN;
            #pragma unroll
            for (int nt = 0; nt < 4; nt++) {
                int c0 = warpN * 32 + nt * 8 + (lane & 3) * 2;
                #pragma unroll
                for (int j = 0; j < 2; j++) {
                    float v = acc[mt][nt][half * 2 + j];
                    if (v <= thr) {
                        int p = atomicAdd(&sCnt[rl], 1);
                        if (p < KSLOT) sCand[rl * KSLOT + p] = packvc(v, codeBase + c0 + j);
                    }
                }
            }
        }
    }
    __syncthreads();

    // write out: only the used candidate slots
    if (tid < 128) {
        int cnt = sCnt[tid];
        size_t o = (size_t)(rowBase + tid) * NTILES + tileN;
        g_tmin[o] = sMin[tid];
        g_tcnt[o] = cnt;
        int c = cnt < KSLOT ? cnt : KSLOT;
        size_t co = o * KSLOT;
        for (int j = 0; j < c; j++) g_tcand[co + j] = sCand[tid * KSLOT + j];
    }
}

// ---------------- kernel 4: warp-per-row candidate gather + exact rescore ----
__global__ __launch_bounds__(256, 3)
void vq_scan_kernel(const float* __restrict__ emb, float* __restrict__ out) {
    const int w = threadIdx.x >> 5, lane = threadIdx.x & 31;
    const int n = blockIdx.x * 8 + w;

    __shared__ int   s_cand[8][WCAND];
    __shared__ float s_tval[8][WCAND];
    __shared__ int   s_cnt[8];
    __shared__ int   s_ovf[8];

    if (lane == 0) { s_cnt[w] = 0; s_ovf[w] = 0; }
    __syncwarp();

    const float* tmrow = g_tmin + (size_t)n * NTILES;
    float m0 = tmrow[lane], m1 = tmrow[lane + 32];
    float mn = fminf(m0, m1);
    #pragma unroll
    for (int o = 16; o; o >>= 1) mn = fminf(mn, __shfl_xor_sync(0xffffffffu, mn, o));
    const float thr = mn + MARGIN;

    #pragma unroll
    for (int tt = 0; tt < 2; tt++) {
        int t = lane + tt * 32;
        float tm = tt ? m1 : m0;
        if (tm <= thr) {
            int cnt = g_tcnt[(size_t)n * NTILES + t];
            if (cnt <= KSLOT) {
                size_t base = ((size_t)n * NTILES + t) * KSLOT;
                for (int c = 0; c < cnt; c++) {
                    unsigned long long cd = g_tcand[base + c];
                    if (unpackv(cd) <= thr) {
                        int p = atomicAdd(&s_cnt[w], 1);
                        if (p < WCAND) {
                            int code = (int)(cd & 0xffffffffu);
                            s_cand[w][p] = code;
                            s_tval[w][p] = g_T[code];
                        } else s_ovf[w] = 1;
                    }
                }
            } else {
                for (int j = 0; j < 128; j++) {
                    int p = atomicAdd(&s_cnt[w], 1);
                    if (p < WCAND) {
                        int code = t * 128 + j;
                        s_cand[w][p] = code;
                        s_tval[w][p] = g_T[code];
                    } else s_ovf[w] = 1;
                }
            }
        }
    }
    __syncwarp();

    const bool full = s_ovf[w] != 0;
    const int total = full ? NCODE : min(s_cnt[w], WCAND);

    if (!full && total == 1) {
        if (lane == 0) {
            int bk = s_cand[w][0];
            g_idx[n] = bk;
            out[OFF_IDX + n] = (float)bk;
            atomicAdd(&g_hist[bk], 1);
        }
        return;
    }

    const float4* zr = (const float4*)(g_zflat + (size_t)n * DIM);
    float4 zv[8];
    #pragma unroll
    for (int j = 0; j < 8; j++) zv[j] = zr[lane + 32 * j];
    const float S = g_S[n];

    float bd = __int_as_float(0x7f800000);
    int   bk = 0x7fffffff;

    for (int c = 0; c < total; c++) {
        int k = full ? c : s_cand[w][c];
        const float4* er = (const float4*)(emb + (size_t)k * DIM);
        float p = 0.f;
        #pragma unroll
        for (int j = 0; j < 8; j++) {
            float4 e = er[lane + 32 * j];
            p = fmaf(zv[j].x, e.x, p);
            p = fmaf(zv[j].y, e.y, p);
            p = fmaf(zv[j].z, e.z, p);
            p = fmaf(zv[j].w, e.w, p);
        }
        #pragma unroll
        for (int o = 16; o; o >>= 1) p += __shfl_down_sync(0xffffffffu, p, o);
        if (lane == 0) {
            float T = full ? g_T[k] : s_tval[w][c];
            float d = __fsub_rn(__fadd_rn(S, T), 2.0f * p);
            if (d < bd || (d == bd && k < bk)) { bd = d; bk = k; }
        }
    }
    if (lane == 0) {
        g_idx[n] = bk;
        out[OFF_IDX + n] = (float)bk;
        atomicAdd(&g_hist[bk], 1);
    }
}

// ---------------- kernel 5: tiled gather + STE + loss (all coalesced) --------
// Tile 32(hw) x 32(c) per block, like the transpose. emb rows read contiguously,
// zflat read coalesced, out written coalesced along hw.
__global__ void vq_gather_kernel(const float* __restrict__ emb,
                                 float* __restrict__ out) {
    __shared__ float tile[32][33];
    __shared__ int   codes[32];
    __shared__ float warpsum[8];
    int b   = blockIdx.z;
    int hw0 = blockIdx.x * 32;
    int c0  = blockIdx.y * 32;
    int tx = threadIdx.x, ty = threadIdx.y;

    if (ty == 0) codes[tx] = g_idx[(b << 10) | (hw0 + tx)];
    __syncthreads();

    float sq = 0.f;
    #pragma unroll
    for (int r = ty; r < 32; r += 8) {
        int n = (b << 10) | (hw0 + r);
        float zv = g_zflat[(size_t)n * DIM + c0 + tx];
        float e  = emb[(size_t)codes[r] * DIM + c0 + tx];
        float diff = __fsub_rn(e, zv);
        tile[r][tx] = __fadd_rn(zv, diff);
        sq = fmaf(diff, diff, sq);
    }
    __syncthreads();

    #pragma unroll
    for (int r = ty; r < 32; r += 8)
        out[((size_t)b << 20) + (size_t)(c0 + r) * HW + hw0 + tx] = tile[tx][r];

    // block-reduce sq -> double atomic
    #pragma unroll
    for (int o = 16; o; o >>= 1) sq += __shfl_down_sync(0xffffffffu, sq, o);
    int lt = ty * 32 + tx;
    int lane = lt & 31, wid = lt >> 5;
    if (lane == 0) warpsum[wid] = sq;
    __syncthreads();
    if (wid == 0) {
        float v = (lane < 8) ? warpsum[lane] : 0.f;
        #pragma unroll
        for (int o = 4; o; o >>= 1) v += __shfl_down_sync(0xffffffffu, v, o);
        if (lane == 0) atomicAdd(&g_loss, (double)v);
    }
}

// ---------------- kernel 6: finalize loss + perplexity -----------------------
__global__ void vq_finalize_kernel(float* __restrict__ out) {
    __shared__ float warpsum[8];
    int tid = threadIdx.x;
    float s = 0.f;
    for (int k = tid; k < NCODE; k += 256) {
        float c = (float)g_hist[k];
        float p = c * (1.0f / (float)NROW);
        s += p * logf(p + 1e-10f);
    }
    #pragma unroll
    for (int o = 16; o; o >>= 1) s += __shfl_down_sync(0xffffffffu, s, o);
    int lane = tid & 31, wid = tid >> 5;
    if (lane == 0) warpsum[wid] = s;
    __syncthreads();
    if (wid == 0) {
        float v = (lane < 8) ? warpsum[lane] : 0.f;
        #pragma unroll
        for (int o = 4; o; o >>= 1) v += __shfl_down_sync(0xffffffffu, v, o);
        if (lane == 0) {
            out[OFF_PERP] = expf(-v);
            double m = g_loss / (double)ZQ_ELEMS;
            float mf = (float)m;
            out[OFF_LOSS] = __fadd_rn(mf, 0.25f * mf);
        }
    }
}

// ---------------- launch ------------------------------------------------------
extern "C" void kernel_launch(void* const* d_in, const int* in_sizes, int n_in,
                              void* d_out, int out_size) {
    const float* z   = (const float*)d_in[0];
    const float* emb = (const float*)d_in[1];
    float* out = (float*)d_out;
    (void)in_sizes; (void)n_in; (void)out_size;

    dim3 tb(32, 8);
    dim3 tg(32, 32, BATCH);
    vq_transpose_kernel<<<tg, tb>>>(z);

    vq_rowsum_kernel<<<(NROW + NCODE) * 32 / 256, 256>>>(emb);

    dim3 mg(NCODE / 128, NROW / 128);
    vq_mm_kernel<<<mg, 256>>>();

    vq_scan_kernel<<<NROW / 8, 256>>>(emb, out);

    vq_gather_kernel<<<tg, tb>>>(emb, out);

    vq_finalize_kernel<<<1, 256>>>(out);
}

// round 17
// speedup vs baseline: 1.1331x; 1.0026x over previous
#include <cuda_runtime.h>
#include <cuda_fp16.h>
#include <math.h>
#include <stdint.h>

// Problem constants
#define BATCH   8
#define DIM     1024
#define HW      1024
#define NROW    8192
#define NCODE   8192
#define ZQ_ELEMS (BATCH*DIM*HW)
#define OFF_LOSS  ZQ_ELEMS
#define OFF_PERP  (ZQ_ELEMS + 1)
#define OFF_IDX   (ZQ_ELEMS + 2)

#define ESCALE 512.0f
#define MARGIN 1e-3f
#define NTILES 64
#define KSLOT  8
#define WCAND  256

// ---------------- device scratch ---------------------------------------------
__device__ float   g_zflat[(size_t)NROW * DIM];
__device__ __half  g_zh[(size_t)NROW * DIM];
__device__ __half  g_eh[(size_t)NCODE * DIM];
__device__ float   g_partS[(size_t)NROW * 32];
__device__ float   g_S[NROW];
__device__ float   g_T[NCODE];
__device__ float   g_tmin[(size_t)NROW * NTILES];
__device__ int     g_tcnt[(size_t)NROW * NTILES];
__device__ unsigned long long g_tcand[(size_t)NROW * NTILES * KSLOT];
__device__ int     g_idx[NROW];
__device__ int     g_hist[NCODE];
__device__ double  g_loss;

// ---------------- PTX helpers -------------------------------------------------
__device__ __forceinline__ uint32_t smem_u32(const void* p) {
    uint32_t a;
    asm("{ .reg .u64 t; cvta.to.shared.u64 t, %1; cvt.u32.u64 %0, t; }" : "=r"(a) : "l"(p));
    return a;
}
__device__ __forceinline__ void cp_async16(uint32_t saddr, const void* gptr) {
    asm volatile("cp.async.cg.shared.global [%0], [%1], 16;" :: "r"(saddr), "l"(gptr));
}
__device__ __forceinline__ void cp_commit() { asm volatile("cp.async.commit_group;" ::: "memory"); }
__device__ __forceinline__ void cp_wait0()  { asm volatile("cp.async.wait_group 0;" ::: "memory"); }

__device__ __forceinline__ void ldsm_x4(uint32_t* r, uint32_t addr) {
    asm volatile("ldmatrix.sync.aligned.m8n8.x4.shared.b16 {%0,%1,%2,%3}, [%4];"
                 : "=r"(r[0]), "=r"(r[1]), "=r"(r[2]), "=r"(r[3]) : "r"(addr));
}
__device__ __forceinline__ void mma16816(float* d, const uint32_t* a, uint32_t b0, uint32_t b1) {
    asm volatile("mma.sync.aligned.m16n8k16.row.col.f32.f16.f16.f32 "
                 "{%0,%1,%2,%3}, {%4,%5,%6,%7}, {%8,%9}, {%0,%1,%2,%3};"
                 : "+f"(d[0]), "+f"(d[1]), "+f"(d[2]), "+f"(d[3])
                 : "r"(a[0]), "r"(a[1]), "r"(a[2]), "r"(a[3]), "r"(b0), "r"(b1));
}
__device__ __forceinline__ unsigned long long packvc(float v, int code) {
    return ((unsigned long long)__float_as_uint(v) << 32) | (unsigned)code;
}
__device__ __forceinline__ float unpackv(unsigned long long p) {
    return __uint_as_float((unsigned)(p >> 32));
}

// ---------------- kernel 1: transpose z -> zflat (fp32+fp16) + partial S -----
__global__ void vq_transpose_kernel(const float* __restrict__ z) {
    __shared__ float tile[32][33];
    int b = blockIdx.z;
    int hw0 = blockIdx.x * 32;
    int c0  = blockIdx.y * 32;
    const float* src = z + ((size_t)b << 20);
    float* dst = g_zflat + ((size_t)b << 20);
    __half* dsth = g_zh + ((size_t)b << 20);
    #pragma unroll
    for (int r = threadIdx.y; r < 32; r += 8)
        tile[r][threadIdx.x] = src[(size_t)(c0 + r) * HW + hw0 + threadIdx.x];
    __syncthreads();
    #pragma unroll
    for (int r = threadIdx.y; r < 32; r += 8) {
        float v = tile[threadIdx.x][r];
        size_t o = (size_t)(hw0 + r) * DIM + c0 + threadIdx.x;
        dst[o]  = v;
        dsth[o] = __float2half_rn(v);
        float sq = v * v;
        #pragma unroll
        for (int s = 16; s; s >>= 1) sq += __shfl_down_sync(0xffffffffu, sq, s);
        if (threadIdx.x == 0)
            g_partS[(((size_t)(b << 10) | (hw0 + r)) << 5) | blockIdx.y] = sq;
    }
}

// ---------------- kernel 2: S combine; emb norms + fp16 convert; zero hist ---
__global__ void vq_rowsum_kernel(const float* __restrict__ emb) {
    int gw   = (blockIdx.x * blockDim.x + threadIdx.x) >> 5;
    int lane = threadIdx.x & 31;
    if (gw >= NROW + NCODE) return;
    if (gw < NROW) {
        float s = g_partS[((size_t)gw << 5) | lane];
        #pragma unroll
        for (int o = 16; o; o >>= 1) s += __shfl_down_sync(0xffffffffu, s, o);
        if (lane == 0) {
            g_S[gw] = s;
            if (gw == 0) g_loss = 0.0;
        }
        return;
    }
    int row = gw - NROW;
    const float4* s4 = (const float4*)(emb + (size_t)row * DIM);
    __half2* eh2 = (__half2*)(g_eh + (size_t)row * DIM);
    float acc = 0.f;
    #pragma unroll 4
    for (int i = lane; i < DIM / 4; i += 32) {
        float4 v = s4[i];
        eh2[i * 2]     = __floats2half2_rn(v.x * ESCALE, v.y * ESCALE);
        eh2[i * 2 + 1] = __floats2half2_rn(v.z * ESCALE, v.w * ESCALE);
        acc += v.x * v.x + v.y * v.y + v.z * v.z + v.w * v.w;
    }
    #pragma unroll
    for (int o = 16; o; o >>= 1) acc += __shfl_down_sync(0xffffffffu, acc, o);
    if (lane == 0) { g_T[row] = acc; g_hist[row] = 0; }
}

// ---------------- kernel 3: fp16 HMMA GEMM (R10 verbatim - FROZEN mainloop) --
#define AS_OFF(s) ((s) * 10240u)
#define BS_OFF(s) (20480u + (s) * 10240u)

__global__ __launch_bounds__(256, 2)
void vq_mm_kernel() {
    __shared__ __align__(128) uint8_t smem[40960];
    const uint32_t sb = smem_u32(smem);
    const int tid = threadIdx.x;
    const int lane = tid & 31, wid = tid >> 5;
    const int warpM = wid >> 2, warpN = wid & 3;
    const int rowBase  = blockIdx.y * 128;
    const int codeBase = blockIdx.x * 128;
    const int tileN = blockIdx.x;

    const int ldrow = tid >> 1;
    const int ldc0  = (tid & 1) * 2;
    const __half* gA = g_zh + (size_t)(rowBase + ldrow) * DIM + ldc0 * 8;
    const __half* gB = g_eh + (size_t)(codeBase + ldrow) * DIM + ldc0 * 8;
    const uint32_t stA = (uint32_t)ldrow * 80u + (uint32_t)ldc0 * 16u;

    const uint32_t a_base = (uint32_t)((warpM * 64 + (lane & 15)) * 80 + ((lane >> 4) * 8) * 2);
    const int grp = lane >> 3;
    const uint32_t b_base = (uint32_t)((warpN * 32 + ((grp >> 1) * 8) + (lane & 7)) * 80
                                       + ((grp & 1) * 8) * 2);

    float acc[4][4][4];
    #pragma unroll
    for (int i = 0; i < 4; i++)
        #pragma unroll
        for (int j = 0; j < 4; j++)
            #pragma unroll
            for (int k = 0; k < 4; k++) acc[i][j][k] = 0.f;

    {
        uint32_t a0 = sb + AS_OFF(0) + stA;
        cp_async16(a0,      gA);
        cp_async16(a0 + 16, gA + 8);
        uint32_t b0 = sb + BS_OFF(0) + stA;
        cp_async16(b0,      gB);
        cp_async16(b0 + 16, gB + 8);
        cp_commit();
    }

    #pragma unroll 1
    for (int kt = 0; kt < 32; kt++) {
        cp_wait0();
        __syncthreads();
        if (kt < 31) {
            int k0 = (kt + 1) * 32;
            int s  = (kt + 1) & 1;
            uint32_t a0 = sb + AS_OFF(s) + stA;
            cp_async16(a0,      gA + k0);
            cp_async16(a0 + 16, gA + k0 + 8);
            uint32_t b0 = sb + BS_OFF(s) + stA;
            cp_async16(b0,      gB + k0);
            cp_async16(b0 + 16, gB + k0 + 8);
            cp_commit();
        }
        const int s = kt & 1;
        const uint32_t As0 = sb + AS_OFF(s) + a_base;
        const uint32_t Bs0 = sb + BS_OFF(s) + b_base;
        #pragma unroll
        for (int ks = 0; ks < 2; ks++) {
            uint32_t a[4][4], b[2][4];
            #pragma unroll
            for (int mt = 0; mt < 4; mt++) ldsm_x4(a[mt], As0 + mt * 16 * 80 + ks * 32);
            #pragma unroll
            for (int pr = 0; pr < 2; pr++)  ldsm_x4(b[pr], Bs0 + pr * 16 * 80 + ks * 32);
            #pragma unroll
            for (int mt = 0; mt < 4; mt++)
                #pragma unroll
                for (int nt = 0; nt < 4; nt++)
                    mma16816(acc[mt][nt], a[mt], b[nt >> 1][(nt & 1) * 2], b[nt >> 1][(nt & 1) * 2 + 1]);
        }
    }
    __syncthreads();

    // ---- lean fused epilogue: per-row tile min + margin candidates ----
    float* sWmin = (float*)smem;
    float* sMin  = (float*)(smem + 2048);
    int*   sCnt  = (int*)(smem + 2560);
    unsigned long long* sCand = (unsigned long long*)(smem + 3072);

    const float inv2 = 2.0f / ESCALE;
    float Sv[4][2], Tv[4][2];
    #pragma unroll
    for (int mt = 0; mt < 4; mt++) {
        int r0 = rowBase + warpM * 64 + mt * 16 + (lane >> 2);
        Sv[mt][0] = g_S[r0]; Sv[mt][1] = g_S[r0 + 8];
    }
    #pragma unroll
    for (int nt = 0; nt < 4; nt++) {
        int c0 = codeBase + warpN * 32 + nt * 8 + (lane & 3) * 2;
        Tv[nt][0] = g_T[c0]; Tv[nt][1] = g_T[c0 + 1];
    }

    #pragma unroll
    for (int mt = 0; mt < 4; mt++)
        #pragma unroll
        for (int nt = 0; nt < 4; nt++)
            #pragma unroll
            for (int half = 0; half < 2; half++)
                #pragma unroll
                for (int j = 0; j < 2; j++)
                    acc[mt][nt][half * 2 + j] =
                        __fsub_rn(__fadd_rn(Sv[mt][half], Tv[nt][j]),
                                  inv2 * acc[mt][nt][half * 2 + j]);

    #pragma unroll
    for (int mt = 0; mt < 4; mt++) {
        #pragma unroll
        for (int half = 0; half < 2; half++) {
            float mn = acc[mt][0][half * 2];
            #pragma unroll
            for (int nt = 0; nt < 4; nt++)
                #pragma unroll
                for (int j = 0; j < 2; j++)
                    mn = fminf(mn, acc[mt][nt][half * 2 + j]);
            mn = fminf(mn, __shfl_xor_sync(0xffffffffu, mn, 1));
            mn = fminf(mn, __shfl_xor_sync(0xffffffffu, mn, 2));
            if ((lane & 3) == 0) {
                int rl = warpM * 64 + mt * 16 + (lane >> 2) + half * 8;
                sWmin[(rl << 2) | warpN] = mn;
            }
        }
    }
    __syncthreads();
    if (tid < 128) {
        float m = fminf(fminf(sWmin[tid * 4], sWmin[tid * 4 + 1]),
                        fminf(sWmin[tid * 4 + 2], sWmin[tid * 4 + 3]));
        sMin[tid] = m;
        sCnt[tid] = 0;
    }
    __syncthreads();

    #pragma unroll
    for (int mt = 0; mt < 4; mt++) {
        #pragma unroll
        for (int half = 0; half < 2; half++) {
            int rl = warpM * 64 + mt * 16 + (lane >> 2) + half * 8;
            float thr = sMin[rl] + MARGIN;
            #pragma unroll
            for (int nt = 0; nt < 4; nt++) {
                int c0 = warpN * 32 + nt * 8 + (lane & 3) * 2;
                #pragma unroll
                for (int j = 0; j < 2; j++) {
                    float v = acc[mt][nt][half * 2 + j];
                    if (v <= thr) {
                        int p = atomicAdd(&sCnt[rl], 1);
                        if (p < KSLOT) sCand[rl * KSLOT + p] = packvc(v, codeBase + c0 + j);
                    }
                }
            }
        }
    }
    __syncthreads();

    if (tid < 128) {
        int cnt = sCnt[tid];
        size_t o = (size_t)(rowBase + tid) * NTILES + tileN;
        g_tmin[o] = sMin[tid];
        g_tcnt[o] = cnt;
        int c = cnt < KSLOT ? cnt : KSLOT;
        size_t co = o * KSLOT;
        for (int j = 0; j < c; j++) g_tcand[co + j] = sCand[tid * KSLOT + j];
    }
}

// ---------------- kernel 4: warp-per-row gather + 2-way ILP exact rescore ----
__global__ __launch_bounds__(256, 3)
void vq_scan_kernel(const float* __restrict__ emb, float* __restrict__ out) {
    const int w = threadIdx.x >> 5, lane = threadIdx.x & 31;
    const int n = blockIdx.x * 8 + w;

    __shared__ int   s_cand[8][WCAND];
    __shared__ float s_tval[8][WCAND];
    __shared__ int   s_cnt[8];
    __shared__ int   s_ovf[8];

    if (lane == 0) { s_cnt[w] = 0; s_ovf[w] = 0; }
    __syncwarp();

    const float* tmrow = g_tmin + (size_t)n * NTILES;
    float m0 = tmrow[lane], m1 = tmrow[lane + 32];
    float mn = fminf(m0, m1);
    #pragma unroll
    for (int o = 16; o; o >>= 1) mn = fminf(mn, __shfl_xor_sync(0xffffffffu, mn, o));
    const float thr = mn + MARGIN;

    #pragma unroll
    for (int tt = 0; tt < 2; tt++) {
        int t = lane + tt * 32;
        float tm = tt ? m1 : m0;
        if (tm <= thr) {
            int cnt = g_tcnt[(size_t)n * NTILES + t];
            if (cnt <= KSLOT) {
                size_t base = ((size_t)n * NTILES + t) * KSLOT;
                for (int c = 0; c < cnt; c++) {
                    unsigned long long cd = g_tcand[base + c];
                    if (unpackv(cd) <= thr) {
                        int p = atomicAdd(&s_cnt[w], 1);
                        if (p < WCAND) {
                            int code = (int)(cd & 0xffffffffu);
                            s_cand[w][p] = code;
                            s_tval[w][p] = g_T[code];
                        } else s_ovf[w] = 1;
                    }
                }
            } else {
                for (int j = 0; j < 128; j++) {
                    int p = atomicAdd(&s_cnt[w], 1);
                    if (p < WCAND) {
                        int code = t * 128 + j;
                        s_cand[w][p] = code;
                        s_tval[w][p] = g_T[code];
                    } else s_ovf[w] = 1;
                }
            }
        }
    }
    __syncwarp();

    const bool full = s_ovf[w] != 0;
    const int total = full ? NCODE : min(s_cnt[w], WCAND);

    if (!full && total == 1) {
        if (lane == 0) {
            int bk = s_cand[w][0];
            g_idx[n] = bk;
            out[OFF_IDX + n] = (float)bk;
            atomicAdd(&g_hist[bk], 1);
        }
        return;
    }

    const float4* zr = (const float4*)(g_zflat + (size_t)n * DIM);
    float4 zv[8];
    #pragma unroll
    for (int j = 0; j < 8; j++) zv[j] = zr[lane + 32 * j];
    const float S = g_S[n];

    float bd = __int_as_float(0x7f800000);
    int   bk = 0x7fffffff;

    // 2-way candidate ILP: both emb rows' loads in flight together.
    // (d,k) lexicographic-min update is order-independent -> idx unchanged.
    for (int c = 0; c < total; c += 2) {
        const bool has2 = (c + 1 < total);
        int k0 = full ? c : s_cand[w][c];
        int k1 = has2 ? (full ? (c + 1) : s_cand[w][c + 1]) : k0;
        const float4* er0 = (const float4*)(emb + (size_t)k0 * DIM);
        const float4* er1 = (const float4*)(emb + (size_t)k1 * DIM);
        float p0 = 0.f, p1 = 0.f;
        #pragma unroll
        for (int j = 0; j < 8; j++) {
            float4 e0 = er0[lane + 32 * j];
            float4 e1 = er1[lane + 32 * j];
            p0 = fmaf(zv[j].x, e0.x, p0);
            p0 = fmaf(zv[j].y, e0.y, p0);
            p0 = fmaf(zv[j].z, e0.z, p0);
            p0 = fmaf(zv[j].w, e0.w, p0);
            p1 = fmaf(zv[j].x, e1.x, p1);
            p1 = fmaf(zv[j].y, e1.y, p1);
            p1 = fmaf(zv[j].z, e1.z, p1);
            p1 = fmaf(zv[j].w, e1.w, p1);
        }
        #pragma unroll
        for (int o = 16; o; o >>= 1) {
            p0 += __shfl_down_sync(0xffffffffu, p0, o);
            p1 += __shfl_down_sync(0xffffffffu, p1, o);
        }
        if (lane == 0) {
            float T0 = full ? g_T[k0] : s_tval[w][c];
            float d0 = __fsub_rn(__fadd_rn(S, T0), 2.0f * p0);
            if (d0 < bd || (d0 == bd && k0 < bk)) { bd = d0; bk = k0; }
            if (has2) {
                float T1 = full ? g_T[k1] : s_tval[w][c + 1];
                float d1 = __fsub_rn(__fadd_rn(S, T1), 2.0f * p1);
                if (d1 < bd || (d1 == bd && k1 < bk)) { bd = d1; bk = k1; }
            }
        }
    }
    if (lane == 0) {
        g_idx[n] = bk;
        out[OFF_IDX + n] = (float)bk;
        atomicAdd(&g_hist[bk], 1);
    }
}

// ---------------- kernel 5: tiled gather + STE + loss (all coalesced) --------
__global__ void vq_gather_kernel(const float* __restrict__ emb,
                                 float* __restrict__ out) {
    __shared__ float tile[32][33];
    __shared__ int   codes[32];
    __shared__ float warpsum[8];
    int b   = blockIdx.z;
    int hw0 = blockIdx.x * 32;
    int c0  = blockIdx.y * 32;
    int tx = threadIdx.x, ty = threadIdx.y;

    if (ty == 0) codes[tx] = g_idx[(b << 10) | (hw0 + tx)];
    __syncthreads();

    float sq = 0.f;
    #pragma unroll
    for (int r = ty; r < 32; r += 8) {
        int n = (b << 10) | (hw0 + r);
        float zv = g_zflat[(size_t)n * DIM + c0 + tx];
        float e  = emb[(size_t)codes[r] * DIM + c0 + tx];
        float diff = __fsub_rn(e, zv);
        tile[r][tx] = __fadd_rn(zv, diff);
        sq = fmaf(diff, diff, sq);
    }
    __syncthreads();

    #pragma unroll
    for (int r = ty; r < 32; r += 8)
        out[((size_t)b << 20) + (size_t)(c0 + r) * HW + hw0 + tx] = tile[tx][r];

    #pragma unroll
    for (int o = 16; o; o >>= 1) sq += __shfl_down_sync(0xffffffffu, sq, o);
    int lt = ty * 32 + tx;
    int lane = lt & 31, wid = lt >> 5;
    if (lane == 0) warpsum[wid] = sq;
    __syncthreads();
    if (wid == 0) {
        float v = (lane < 8) ? warpsum[lane] : 0.f;
        #pragma unroll
        for (int o = 4; o; o >>= 1) v += __shfl_down_sync(0xffffffffu, v, o);
        if (lane == 0) atomicAdd(&g_loss, (double)v);
    }
}

// ---------------- kernel 6: finalize loss + perplexity -----------------------
__global__ void vq_finalize_kernel(float* __restrict__ out) {
    __shared__ float warpsum[8];
    int tid = threadIdx.x;
    float s = 0.f;
    for (int k = tid; k < NCODE; k += 256) {
        float c = (float)g_hist[k];
        float p = c * (1.0f / (float)NROW);
        s += p * logf(p + 1e-10f);
    }
    #pragma unroll
    for (int o = 16; o; o >>= 1) s += __shfl_down_sync(0xffffffffu, s, o);
    int lane = tid & 31, wid = tid >> 5;
    if (lane == 0) warpsum[wid] = s;
    __syncthreads();
    if (wid == 0) {
        float v = (lane < 8) ? warpsum[lane] : 0.f;
        #pragma unroll
        for (int o = 4; o; o >>= 1) v += __shfl_down_sync(0xffffffffu, v, o);
        if (lane == 0) {
            out[OFF_PERP] = expf(-v);
            double m = g_loss / (double)ZQ_ELEMS;
            float mf = (float)m;
            out[OFF_LOSS] = __fadd_rn(mf, 0.25f * mf);
        }
    }
}

// ---------------- launch ------------------------------------------------------
extern "C" void kernel_launch(void* const* d_in, const int* in_sizes, int n_in,
                              void* d_out, int out_size) {
    const float* z   = (const float*)d_in[0];
    const float* emb = (const float*)d_in[1];
    float* out = (float*)d_out;
    (void)in_sizes; (void)n_in; (void)out_size;

    dim3 tb(32, 8);
    dim3 tg(32, 32, BATCH);
    vq_transpose_kernel<<<tg, tb>>>(z);

    vq_rowsum_kernel<<<(NROW + NCODE) * 32 / 256, 256>>>(emb);

    dim3 mg(NCODE / 128, NROW / 128);
    vq_mm_kernel<<<mg, 256>>>();

    vq_scan_kernel<<<NROW / 8, 256>>>(emb, out);

    vq_gather_kernel<<<tg, tb>>>(emb, out);

    vq_finalize_kernel<<<1, 256>>>(out);
}